// round 9
// baseline (speedup 1.0000x reference)
#include <cuda_runtime.h>
#include <cuda_fp16.h>
#include <math.h>

#define BATCH 32
#define T     1024
#define DIM   64
#define NW    8                 // DP warps per batch (128 rows each)
#define NCH   76                // chunks of 16 steps: 1216 steps
#define SPAD  1248              // NCH*16 + 32 FIFO pad
#define HANDW 1220              // handoff row width (halves)
#define SRMAX 221               // epilogue s-rows per tile
#define NUNITS 380              // producer units: 116*3 + 32
#define NTILES 8192             // 32 b * 8 w * 32 jt
#define HAND_BYTES ((NW + 1) * HANDW * 2)     // 21960
#define PROG_OFF   HAND_BYTES
#define DPUNIT_OFF 22016
// unit floats: As 64*128 + Bs 64*32 + na_s 128 + nb4 128
#define UNIT_F     (64 * 128 + 64 * 32 + 256)
#define UNIT_BYTES (UNIT_F * 4)               // 41984
#define SMEM_DYN   (3 * UNIT_BYTES)           // 125952

// fp16 cost^2, skew-slotted: g_cst[((b*NW+w)*SPAD + s)*128 + i] holds
// cost[128w+i][s - phi(i)], phi(i) = 6*(i>>2) + (i&3). Invalid = +INF.
__device__ __half g_cst[(size_t)BATCH * NW * SPAD * 128];
__device__ float g_dists[BATCH];
__device__ int   g_flag[BATCH * NW * 32];
__device__ unsigned char g_pairs[256];

__device__ __forceinline__ unsigned hmin2u(unsigned a, unsigned b) {
    __half2 r = __hmin2(*reinterpret_cast<__half2*>(&a), *reinterpret_cast<__half2*>(&b));
    return *reinterpret_cast<unsigned*>(&r);
}
__device__ __forceinline__ unsigned hmax2u(unsigned a, unsigned b) {
    __half2 r = __hmax2(*reinterpret_cast<__half2*>(&a), *reinterpret_cast<__half2*>(&b));
    return *reinterpret_cast<unsigned*>(&r);
}
__device__ __forceinline__ int ld_acq_gpu(const int* p) {
    int v; asm volatile("ld.acquire.gpu.s32 %0, [%1];" : "=r"(v) : "l"(p) : "memory");
    return v;
}

#define UBAR(id) asm volatile("bar.sync %0, %1;" :: "r"(id), "r"(128) : "memory")

// ---------------------------------------------------------------------------
// fill: INF boundary slots [0,189) and [1024,SPAD); zero flags; build order.
// ---------------------------------------------------------------------------
__global__ __launch_bounds__(256) void fill_kernel() {
    int cta = blockIdx.x;                       // 256 CTAs, one per (b,w)
    unsigned* p32 = (unsigned*)(g_cst + (size_t)cta * SPAD * 128);
    const int NS = 189 + (SPAD - 1024);
    for (int v = threadIdx.x; v < NS * 64; v += 256) {
        int sr = v >> 6, q = v & 63;
        int s = (sr < 189) ? sr : (1024 + sr - 189);
        p32[(size_t)s * 64 + q] = 0x7C007C00u;
    }
    int fi = cta * 256 + threadIdx.x;
    if (fi < BATCH * NW * 32) g_flag[fi] = 0;
    if (cta == 0 && threadIdx.x == 0) {
        int idx = 0;
        for (int m = 0; m <= 80; m++)
            for (int w = 0; w < 8; w++) {
                int jt = m - 7 * w;
                if (jt >= 0 && jt < 32) g_pairs[idx++] = (unsigned char)(w * 32 + jt);
            }
    }
}

// ---------------------------------------------------------------------------
// Producer unit: 128 threads, k-major smem, 8x4 micro-tile with LDS.128
// operand fetch (3 LDS.128 + 32 FFMA per k). Norms computed during load.
// ---------------------------------------------------------------------------
__device__ void producer_part(const float* __restrict__ A, const float* __restrict__ B,
                              float* __restrict__ base, int barid, int unit, int t128) {
    float* As  = base;              // [64][128] k-major
    float* Bs  = base + 64 * 128;   // [64][32]  k-major
    float* na_s = Bs + 64 * 32;     // [128]
    float* nb4  = na_s + 128;       // [4][32] partial B norms
    const int tx = t128 & 7;
    const int ty = t128 >> 3;

    for (int p = unit; p < NTILES; p += NUNITS) {
        int pr = g_pairs[p >> 5];
        int b = p & 31, w = pr >> 5, jt = pr & 31;
        int j0 = jt * 32;

        // A tile transpose-load + row norm (thread t owns row i = t)
        {
            const float4* Ar = (const float4*)(A + ((size_t)b * T + w * 128 + t128) * DIM);
            float na = 0.f;
#pragma unroll
            for (int kq = 0; kq < 16; kq++) {
                float4 v = Ar[kq];
                na += v.x * v.x + v.y * v.y + v.z * v.z + v.w * v.w;
                As[(kq * 4 + 0) * 128 + t128] = v.x;
                As[(kq * 4 + 1) * 128 + t128] = v.y;
                As[(kq * 4 + 2) * 128 + t128] = v.z;
                As[(kq * 4 + 3) * 128 + t128] = v.w;
            }
            na_s[t128] = na;
        }
        // B tile transpose-load + partial norms (4 threads per row)
        {
            int j = t128 & 31, q4 = t128 >> 5;
            const float4* Br = (const float4*)(B + ((size_t)b * T + j0 + j) * DIM) + q4 * 4;
            float nb = 0.f;
#pragma unroll
            for (int kk = 0; kk < 4; kk++) {
                float4 v = Br[kk];
                int k0 = q4 * 16 + kk * 4;
                nb += v.x * v.x + v.y * v.y + v.z * v.z + v.w * v.w;
                Bs[(k0 + 0) * 32 + j] = v.x;
                Bs[(k0 + 1) * 32 + j] = v.y;
                Bs[(k0 + 2) * 32 + j] = v.z;
                Bs[(k0 + 3) * 32 + j] = v.w;
            }
            nb4[q4 * 32 + j] = nb;
        }
        UBAR(barid);

        float acc[8][4];
#pragma unroll
        for (int r = 0; r < 8; r++)
#pragma unroll
            for (int c = 0; c < 4; c++) acc[r][c] = 0.f;

#pragma unroll 8
        for (int k = 0; k < DIM; k++) {
            float4 a0 = *(const float4*)&As[k * 128 + ty * 8];
            float4 a1 = *(const float4*)&As[k * 128 + ty * 8 + 4];
            float4 b0 = *(const float4*)&Bs[k * 32 + tx * 4];
            float ar[8] = {a0.x, a0.y, a0.z, a0.w, a1.x, a1.y, a1.z, a1.w};
            float br[4] = {b0.x, b0.y, b0.z, b0.w};
#pragma unroll
            for (int r = 0; r < 8; r++)
#pragma unroll
                for (int c = 0; c < 4; c++) acc[r][c] += ar[r] * br[c];
        }
        UBAR(barid);                 // As reads done; reuse as Ch

        __half* Ch = (__half*)As;    // [128][34]
        {
            float nar[8], nbr[4];
#pragma unroll
            for (int r = 0; r < 8; r++) nar[r] = na_s[ty * 8 + r];
#pragma unroll
            for (int c = 0; c < 4; c++)
                nbr[c] = nb4[tx * 4 + c] + nb4[32 + tx * 4 + c]
                       + nb4[64 + tx * 4 + c] + nb4[96 + tx * 4 + c];
#pragma unroll
            for (int r = 0; r < 8; r++)
#pragma unroll
                for (int c = 0; c < 4; c++) {
                    float sq = nar[r] + nbr[c] - 2.0f * acc[r][c];
                    Ch[(ty * 8 + r) * 34 + (tx * 4 + c)] = __float2half_rn(fmaxf(sq, 1e-12f));
                }
        }
        UBAR(barid);

        // Skewed emit: slot s = j + phi(i); sr = s - j0 in [0, SRMAX).
        const int wid = t128 >> 5, lane = t128 & 31;
        size_t sbase = ((size_t)(b * NW + w) * SPAD + j0) * 128;
#pragma unroll 1
        for (int it = 0; it < 56; it++) {
            int sr = it * 4 + wid;
            if (sr < SRMAX) {
                int aq = sr / 6, bq = sr - 6 * aq;
                int ihi = 4 * aq + (bq < 3 ? bq : 3);
                if (ihi > 127) ihi = 127;
                int i = ihi - 31 + lane;
                if (i >= 0) {
                    int jr = sr - (6 * (i >> 2) + (i & 3));
                    if (jr >= 0 && jr < 32)
                        g_cst[sbase + (size_t)sr * 128 + i] = Ch[i * 34 + jr];
                }
            }
        }
        __threadfence();
        UBAR(barid);
        if (t128 == 0)
            ((volatile int*)g_flag)[(b * NW + w) * 32 + jt] = 1;
    }
}

// ---------------------------------------------------------------------------
// DP part: warps 4..11 of DP CTAs (priority over producer wid 0..3).
// E=2-skew systolic engine; chunks gated on cumulative tile flags.
// ---------------------------------------------------------------------------
__device__ void dp_part(int b, char* smem) {
    unsigned short* hand = (unsigned short*)smem;
    int* progress = (int*)(smem + PROG_OFF);
    const int tid0 = threadIdx.x - 128, w = tid0 >> 5, lane = tid0 & 31;

    for (int v = tid0; v < (NW + 1) * HANDW / 2; v += 256)
        ((unsigned*)hand)[v] = 0x7C007C00u;
    if (lane == 0) progress[w] = 0;
    asm volatile("bar.sync 5, 256;" ::: "memory");

    const unsigned short* hrow = &hand[((w == 0) ? NW : (w - 1)) * HANDW];
    unsigned wrow;   // smem addr; +s*2 -> hand[w][s-189]
    {
        unsigned base;
        asm("{ .reg .u64 t; cvta.to.shared.u64 t, %1; cvt.u32.u64 %0, t; }"
            : "=r"(base) : "l"(&hand[w * HANDW]));
        wrow = base - 378u;
    }

    const int fbase = (b * NW + w) * 32;
    int done = 0;
    while (ld_acq_gpu(&g_flag[fbase]) == 0) __nanosleep(128);
    done = 1;

    const __half* cp = g_cst + (size_t)(b * NW + w) * SPAD * 128 + lane * 4;
    uint2 fA[16], fB[16];
#pragma unroll
    for (int q = 0; q < 16; q++) fA[q] = *(const uint2*)(cp + (size_t)q * 128);
#pragma unroll
    for (int q = 0; q < 16; q++) fB[q] = *(const uint2*)(cp + (size_t)(16 + q) * 128);

    const unsigned INF2 = 0x7C007C00u;
    unsigned A = INF2, B = INF2, upAp = INF2, upBp = INF2;
    unsigned sh0 = INF2, sh1 = INF2;
    unsigned hv0 = INF2, hv1 = INF2, hv2 = INF2;
    const bool isl0 = (lane == 0);
    const bool fix0 = (w == 0) && isl0;
    const unsigned p31 = (lane == 31) ? 1u : 0u;
    const __half* cq = cp;

#define DP_STEP(kk, F, ROFF, FIRST)                                            \
    {                                                                          \
        const int s = sbase + (kk);                                            \
        uint2 cw = F[kk];                                                      \
        F[kk] = *(const uint2*)(cq + (size_t)((kk) + (ROFF)) * 128);           \
        unsigned shu = isl0 ? hv0 : sh0;                                       \
        unsigned upA = __byte_perm(shu, A, 0x5432);                            \
        unsigned upB = __byte_perm(A, B, 0x5432);                              \
        unsigned nA = hmax2u(cw.x, hmin2u(hmin2u(upA, upAp), A));              \
        unsigned nB = hmax2u(cw.y, hmin2u(hmin2u(upB, upBp), B));              \
        if ((FIRST) && (kk) == 0) {                                            \
            if (fix0) nA = (nA & 0xFFFF0000u) | (cw.x & 0xFFFFu);              \
        }                                                                      \
        unsigned pr = p31 & (unsigned)(s >= 189);                              \
        asm volatile(                                                          \
            "{ .reg .pred p; setp.ne.u32 p, %0, 0; @p st.shared.u16 [%1], %2; }" \
            :: "r"(pr), "r"(wrow + (unsigned)s * 2),                           \
               "h"((unsigned short)(nB >> 16)));                               \
        unsigned shn = __shfl_up_sync(0xffffffffu, B, 1);                      \
        sh0 = sh1; sh1 = shn;                                                  \
        upAp = upA; upBp = upB;                                                \
        A = nA; B = nB;                                                        \
        hv0 = hv1; hv1 = hv2;                                                  \
        hv2 = ((unsigned)hrow[s + 3]) << 16;                                   \
    }

    for (int td = 0; td < NCH / 2; td++) {
        {   // gate: chunk td refills read slots <= 32*td+63 -> tiles <= td+1
            int need = td + 2; if (need > 32) need = 32;
            while (done < need) {
                if (ld_acq_gpu(&g_flag[fbase + done]) != 0) done++;
                else __nanosleep(64);
            }
        }
        if (w) {
            int need = 2 * td + 14; if (need > NCH) need = NCH;
            while (((volatile int*)progress)[w - 1] < need) __nanosleep(32);
            __threadfence_block();
        }
        if (td == 0) {
            hv0 = ((unsigned)hrow[0]) << 16;
            hv1 = ((unsigned)hrow[1]) << 16;
            hv2 = ((unsigned)hrow[2]) << 16;
        }
        {
            const int sbase = 32 * td;
#pragma unroll
            for (int kk = 0; kk < 16; kk++) DP_STEP(kk, fA, 32, (td == 0))
        }
        __syncwarp();
        __threadfence_block();
        if (lane == 0) ((volatile int*)progress)[w] = 2 * td + 1;
        {
            const int sbase = 32 * td + 16;
#pragma unroll
            for (int kk = 0; kk < 16; kk++) DP_STEP(kk, fB, 48, false)
        }
        __syncwarp();
        __threadfence_block();
        if (lane == 0) ((volatile int*)progress)[w] = 2 * td + 2;
        cq += 32 * 128;
    }
#undef DP_STEP

    asm volatile("bar.sync 5, 256;" ::: "memory");
    if (tid0 == 0)
        g_dists[b] = sqrtf(__half2float(__ushort_as_half(hand[7 * HANDW + 1023])));
}

// ---------------------------------------------------------------------------
// Fused persistent kernel, 148 CTAs (all wave-1 resident).
//   CTA 0..31:  tids 0..127 producer unit (wid 0..3, LOW arbiter priority),
//               tids 128..383 DP warps (wid 4..11, HIGH priority).
//   CTA 32..147: 3 producer units.
// ---------------------------------------------------------------------------
__global__ void __launch_bounds__(384, 1) fused_kernel(const float* __restrict__ A,
                                                       const float* __restrict__ B) {
    extern __shared__ char smem[];
    const int cta = blockIdx.x, tid = threadIdx.x;
    if (cta < BATCH) {
        if (tid < 128)
            producer_part(A, B, (float*)(smem + DPUNIT_OFF), 1, 348 + cta, tid);
        else
            dp_part(cta, smem);
    } else {
        int ul = tid >> 7;
        producer_part(A, B, (float*)(smem + ul * UNIT_BYTES), 1 + ul,
                      (cta - 32) * 3 + ul, tid & 127);
    }
}

// ---------------------------------------------------------------------------
__global__ void finish_kernel(float* __restrict__ out) {
    int t = threadIdx.x;
    float v = g_dists[t];
#pragma unroll
    for (int o = 16; o; o >>= 1) v += __shfl_xor_sync(0xffffffffu, v, o);
    if (t == 0) out[0] = v * (1.0f / BATCH);
}

extern "C" void kernel_launch(void* const* d_in, const int* in_sizes, int n_in,
                              void* d_out, int out_size) {
    const float* pred = (const float*)d_in[0];
    const float* targ = (const float*)d_in[1];
    cudaFuncSetAttribute(fused_kernel, cudaFuncAttributeMaxDynamicSharedMemorySize, SMEM_DYN);
    fill_kernel<<<BATCH * NW, 256>>>();
    fused_kernel<<<148, 384, SMEM_DYN>>>(pred, targ);
    finish_kernel<<<1, 32>>>((float*)d_out);
}